// round 10
// baseline (speedup 1.0000x reference)
#include <cuda_runtime.h>
#include <cuda_fp16.h>
#include <cstdint>

// ---------------- problem constants ----------------
static constexpr int NB    = 16;
static constexpr int CIN   = 64;
static constexpr int COUT  = 64;
static constexpr int HH    = 192;
static constexpr int WW    = 192;
static constexpr int HW    = HH * WW;          // 36864
static constexpr int HID   = 17;
static constexpr int KDY   = 4;
static constexpr int NGRP  = 8;
static constexpr float TEMP = 30.0f;
static constexpr float NEG_SLOPE = 0.01f;

// conv tiling: CTA = 1 sample x (4 rows x 96 cols) output, all 64 couts.
// 12 warps; warp = all 64 couts x 32 px (row = wid/3, colbase = (wid%3)*32).
static constexpr int TROWS = 4;
static constexpr int TCOLS = 96;
static constexpr int SLAB_W   = TCOLS + 2;     // 98
static constexpr int SLAB_R   = TROWS + 2;     // 6
static constexpr int SLAB_PIX = SLAB_R * SLAB_W; // 588
static constexpr int NTHR  = 384;

// smem layout (bytes): x slab (fp16, 128B/pixel) + ALL 9 taps of filter fragments
static constexpr int SMEM_SXH = 0;
static constexpr int SMEM_SF  = SLAB_PIX * 128;            // 75264
static constexpr int CONV_SMEM = SMEM_SF + 9 * 8192;       // 148992

// ---------------- device scratch ----------------
__device__ float g_pooled[NB][CIN];
__device__ float g_attn[NB][KDY];
__device__ float g_hsum[HH * NB * CIN];        // per-(h) pool partials [h][b*64+c]
__device__ __half g_xh[(size_t)NB * HH * WW * CIN];   // x as NHWC fp16 (75.5 MB)
// filter fragments (single fp16): [b][tap][kb(4)][m(4)][lane(32)] x uint4 => 1.18 MB
__device__ uint4 g_ffrag4[NB * 9 * 512];
__device__ float g_part[NB * NGRP * 96 * 2];   // per-conv-CTA GN partials (sum, sumsq)
__device__ float g_mean[NB * NGRP];
__device__ float g_rstd[NB * NGRP];

// ---------------- PTX helpers (portable: sm_80-era only) ----------------
__device__ __forceinline__ uint32_t smem_u32(const void* p) {
    uint32_t a;
    asm("{ .reg .u64 t; cvta.to.shared.u64 t, %1; cvt.u32.u64 %0, t; }" : "=r"(a) : "l"(p));
    return a;
}
__device__ __forceinline__ void ldsm_x4(uint32_t* r, uint32_t addr) {
    asm volatile("ldmatrix.sync.aligned.m8n8.x4.shared.b16 {%0,%1,%2,%3}, [%4];"
        : "=r"(r[0]), "=r"(r[1]), "=r"(r[2]), "=r"(r[3]) : "r"(addr));
}
__device__ __forceinline__ void mma16816(float* d, const uint32_t* a, const uint32_t* b) {
    asm volatile("mma.sync.aligned.m16n8k16.row.col.f32.f16.f16.f32 "
        "{%0,%1,%2,%3}, {%4,%5,%6,%7}, {%8,%9}, {%0,%1,%2,%3};"
        : "+f"(d[0]), "+f"(d[1]), "+f"(d[2]), "+f"(d[3])
        : "r"(a[0]), "r"(a[1]), "r"(a[2]), "r"(a[3]), "r"(b[0]), "r"(b[1]));
}
__device__ __forceinline__ uint32_t pack_h2(__half lo, __half hi) {
    return (uint32_t)__half_as_ushort(lo) | ((uint32_t)__half_as_ushort(hi) << 16);
}
__device__ __forceinline__ void cp_async16(uint32_t dst, const void* src, uint32_t sz) {
    asm volatile("cp.async.cg.shared.global [%0], [%1], 16, %2;"
                 :: "r"(dst), "l"(src), "r"(sz) : "memory");
}
__device__ __forceinline__ void cp_commit_wait() {
    asm volatile("cp.async.commit_group;" ::: "memory");
    asm volatile("cp.async.wait_group 0;" ::: "memory");
}

// ---------------- stage 0: NCHW f32 -> NHWC fp16 transpose + pool partials ----------------
__global__ void prep_kernel(const float* __restrict__ x) {
    const int h = blockIdx.x, b = blockIdx.y;
    __shared__ __align__(16) char st[WW * 128];      // 24576 B
    const int tid = threadIdx.x;

    for (int i = tid; i < CIN * WW; i += 256) {
        int c = i / WW, w = i - c * WW;
        float v = x[(((size_t)b * CIN + c) * HH + h) * WW + w];
        uint32_t off = (uint32_t)(w * 128 + (((c >> 3) ^ (w & 7)) << 4) + (c & 7) * 2);
        *(__half*)(st + off) = __float2half_rn(v);
    }
    __syncthreads();

    if (tid < CIN) {
        int c = tid, gr = c >> 3, c7 = (c & 7) * 2;
        float s = 0.f;
        for (int w = 0; w < WW; ++w)
            s += __half2float(*(const __half*)(st + w * 128 + ((gr ^ (w & 7)) << 4) + c7));
        g_hsum[h * (NB * CIN) + b * CIN + c] = s;
    }

    uint4* dst = (uint4*)(g_xh + ((size_t)(b * HH + h) * WW) * CIN);
    for (int i = tid; i < WW * 8; i += 256) {
        int w = i >> 3, c8 = i & 7;
        uint32_t off = (uint32_t)(w * 128 + ((c8 ^ (w & 7)) << 4));
        dst[i] = *(const uint4*)(st + off);
    }
}

// ---------------- stage 1: finalize pool ----------------
__global__ void pool2_kernel() {
    int bc = blockIdx.x * 256 + threadIdx.x;
    float s = 0.f;
    for (int h = 0; h < HH; ++h) s += g_hsum[h * (NB * CIN) + bc];
    g_pooled[bc >> 6][bc & 63] = s * (1.0f / HW);
}

// ---------------- stage 2: attention MLP + softmax ----------------
__global__ void attn_kernel(const float* __restrict__ w1,
                            const float* __restrict__ w2,
                            const float* __restrict__ b2) {
    int b = threadIdx.x;
    if (b >= NB) return;
    float h[HID];
    #pragma unroll
    for (int j = 0; j < HID; j++) {
        float s = 0.f;
        for (int c = 0; c < CIN; c++) s += g_pooled[b][c] * w1[j * CIN + c];
        h[j] = fmaxf(s, 0.f);
    }
    float sc[KDY];
    float m = -1e30f;
    #pragma unroll
    for (int k = 0; k < KDY; k++) {
        float s = b2[k];
        for (int j = 0; j < HID; j++) s += h[j] * w2[k * HID + j];
        sc[k] = s / TEMP;
        m = fmaxf(m, sc[k]);
    }
    float tot = 0.f;
    #pragma unroll
    for (int k = 0; k < KDY; k++) { sc[k] = expf(sc[k] - m); tot += sc[k]; }
    #pragma unroll
    for (int k = 0; k < KDY; k++) g_attn[b][k] = sc[k] / tot;
}

// ---------------- stage 3: synthesize filters into mma A-fragment order ----------------
__global__ void filter_frag_kernel(const float* __restrict__ w) {
    int n = blockIdx.x * 256 + threadIdx.x;
    if (n >= NB * 9 * 512) return;
    int lane = n & 31;
    int m    = (n >> 5) & 3;
    int kb   = (n >> 7) & 3;
    int tap  = (n >> 9) % 9;
    int b    = n / (9 * 512);
    float at0 = g_attn[b][0], at1 = g_attn[b][1], at2 = g_attn[b][2], at3 = g_attn[b][3];
    int g = lane >> 2, t2 = (lane & 3) * 2;
    int o0 = m * 16 + g;
    int c0 = kb * 16 + t2;
    uint32_t regs[4];
    #pragma unroll
    for (int rr = 0; rr < 4; ++rr) {
        int o = o0 + (rr & 1) * 8;
        int cA = c0 + (rr >> 1) * 8;
        float fv[2];
        #pragma unroll
        for (int e = 0; e < 2; ++e) {
            int c = cA + e;
            int base = (o * 64 + c) * 9 + tap;
            fv[e] = at0 * w[base] + at1 * w[base + 4096 * 9]
                  + at2 * w[base + 2 * 4096 * 9] + at3 * w[base + 3 * 4096 * 9];
        }
        regs[rr] = pack_h2(__float2half_rn(fv[0]), __float2half_rn(fv[1]));
    }
    g_ffrag4[n] = make_uint4(regs[0], regs[1], regs[2], regs[3]);
}

// ---------------- stage 4: pipelined mma.sync fp16 conv + fused GN stats ----------------
__global__ __launch_bounds__(NTHR, 1) void conv_mma_kernel(float* __restrict__ y) {
    extern __shared__ char smem[];
    const uint32_t smem_base = smem_u32(smem);
    const int tid = threadIdx.x, lane = tid & 31, wid = tid >> 5;
    const int b  = blockIdx.z;
    const int h0 = blockIdx.y * TROWS;
    const int w0 = blockIdx.x * TCOLS;

    // ---- stage x slab + filters via cp.async ----
    {
        const __half* xhb = g_xh + (size_t)b * HH * WW * CIN;
        for (int e = tid; e < SLAB_PIX * 8; e += NTHR) {
            int pix = e >> 3, ch = e & 7;
            int r = pix / SLAB_W, cc = pix - r * SLAB_W;
            int hh = h0 + r - 1, ww = w0 + cc - 1;
            bool ok = (hh >= 0) && (hh < HH) && (ww >= 0) && (ww < WW);
            uint32_t dst = smem_base + SMEM_SXH
                         + (uint32_t)(pix * 128 + ((ch ^ (pix & 7)) << 4));
            const void* src = ok
                ? (const void*)(xhb + ((size_t)hh * WW + ww) * CIN + ch * 8)
                : (const void*)xhb;
            cp_async16(dst, src, ok ? 16u : 0u);
        }
        const uint4* src = g_ffrag4 + (size_t)(b * 9) * 512;
        for (int e = tid; e < 9 * 512; e += NTHR)
            cp_async16(smem_base + SMEM_SF + e * 16, src + e, 16u);
    }
    cp_commit_wait();
    __syncthreads();

    const int row     = wid / 3;                 // 0..3
    const int colbase = (wid - row * 3) * 32;    // 0/32/64

    const int gsel = lane >> 3, l7 = lane & 7;
    const int pix_lane = (gsel >> 1) * 8 + l7;
    const int ch_lane  = gsel & 1;

    float acc[16][4];
    #pragma unroll
    for (int i = 0; i < 16; i++)
        #pragma unroll
        for (int j = 0; j < 4; j++) acc[i][j] = 0.f;

    // double-buffered operands
    uint4    aH[2][4];
    uint32_t bh[2][8];

    const uint32_t sf_base = smem_base + SMEM_SF + (uint32_t)lane * 16u;

    #define LOAD_IT(IT, BUF) do {                                                   \
        const int _tap = (IT) >> 2, _kb = (IT) & 3;                                 \
        const int _dh = _tap / 3, _dw = _tap - 3 * _dh;                             \
        const int _pb = (row + _dh) * SLAB_W + colbase + _dw + pix_lane;            \
        const int _ck = _kb * 2 + ch_lane;                                          \
        uint32_t _fb = sf_base + (uint32_t)((_tap * 512 + _kb * 128) * 16);         \
        asm volatile("ld.shared.v4.b32 {%0,%1,%2,%3}, [%4];"                        \
            : "=r"(aH[BUF][0].x), "=r"(aH[BUF][0].y), "=r"(aH[BUF][0].z), "=r"(aH[BUF][0].w) : "r"(_fb)); \
        asm volatile("ld.shared.v4.b32 {%0,%1,%2,%3}, [%4];"                        \
            : "=r"(aH[BUF][1].x), "=r"(aH[BUF][1].y), "=r"(aH[BUF][1].z), "=r"(aH[BUF][1].w) : "r"(_fb + 512)); \
        asm volatile("ld.shared.v4.b32 {%0,%1,%2,%3}, [%4];"                        \
            : "=r"(aH[BUF][2].x), "=r"(aH[BUF][2].y), "=r"(aH[BUF][2].z), "=r"(aH[BUF][2].w) : "r"(_fb + 1024)); \
        asm volatile("ld.shared.v4.b32 {%0,%1,%2,%3}, [%4];"                        \
            : "=r"(aH[BUF][3].x), "=r"(aH[BUF][3].y), "=r"(aH[BUF][3].z), "=r"(aH[BUF][3].w) : "r"(_fb + 1536)); \
        int _p0 = _pb;                                                              \
        ldsm_x4(&bh[BUF][0], smem_base + (uint32_t)(_p0 * 128 + ((_ck ^ (_p0 & 7)) << 4))); \
        int _p1 = _pb + 16;                                                         \
        ldsm_x4(&bh[BUF][4], smem_base + (uint32_t)(_p1 * 128 + ((_ck ^ (_p1 & 7)) << 4))); \
    } while (0)

    #define MMA_IT(BUF) do {                                                        \
        _Pragma("unroll")                                                           \
        for (int _m = 0; _m < 4; ++_m) {                                            \
            mma16816(acc[_m * 4 + 0], (const uint32_t*)&aH[BUF][_m], &bh[BUF][0]);  \
            mma16816(acc[_m * 4 + 1], (const uint32_t*)&aH[BUF][_m], &bh[BUF][2]);  \
            mma16816(acc[_m * 4 + 2], (const uint32_t*)&aH[BUF][_m], &bh[BUF][4]);  \
            mma16816(acc[_m * 4 + 3], (const uint32_t*)&aH[BUF][_m], &bh[BUF][6]);  \
        }                                                                           \
    } while (0)

    LOAD_IT(0, 0);
    #pragma unroll
    for (int it = 0; it < 36; ++it) {
        if (it < 35) {
            if (it & 1) LOAD_IT(it + 1, 0); else LOAD_IT(it + 1, 1);
        }
        if (it & 1) MMA_IT(1); else MMA_IT(0);
    }
    #undef LOAD_IT
    #undef MMA_IT

    // ---- epilogue 1: write y ----
    {
        const int g = lane >> 2, t2 = (lane & 3) * 2;
        const int h = h0 + row;
        #pragma unroll
        for (int m = 0; m < 4; ++m) {
            float* yb = y + ((size_t)(b * 64 + m * 16 + g)) * HW + (size_t)h * WW
                      + w0 + colbase + t2;
            #pragma unroll
            for (int ni = 0; ni < 4; ++ni) {
                *(float2*)(yb + ni * 8) =
                    make_float2(acc[m * 4 + ni][0], acc[m * 4 + ni][1]);
                *(float2*)(yb + ni * 8 + (size_t)8 * HW) =
                    make_float2(acc[m * 4 + ni][2], acc[m * 4 + ni][3]);
            }
        }
    }

    // ---- epilogue 2: GN partial stats (deterministic, no atomics) ----
    // acc[m*4+ni][0,1] -> group 2m ; [2,3] -> group 2m+1
    {
        float ps[16];
        #pragma unroll
        for (int j = 0; j < 16; ++j) ps[j] = 0.f;
        #pragma unroll
        for (int m = 0; m < 4; ++m)
            #pragma unroll
            for (int ni = 0; ni < 4; ++ni) {
                float a0 = acc[m * 4 + ni][0], a1 = acc[m * 4 + ni][1];
                float a2 = acc[m * 4 + ni][2], a3 = acc[m * 4 + ni][3];
                ps[(2 * m) * 2 + 0]     += a0 + a1;
                ps[(2 * m) * 2 + 1]     += a0 * a0 + a1 * a1;
                ps[(2 * m + 1) * 2 + 0] += a2 + a3;
                ps[(2 * m + 1) * 2 + 1] += a2 * a2 + a3 * a3;
            }
        #pragma unroll
        for (int off = 16; off > 0; off >>= 1)
            #pragma unroll
            for (int j = 0; j < 16; ++j)
                ps[j] += __shfl_xor_sync(0xFFFFFFFFu, ps[j], off);

        __shared__ float sh_p[12][16];
        if (lane == 0)
            #pragma unroll
            for (int j = 0; j < 16; ++j) sh_p[wid][j] = ps[j];
        __syncthreads();

        if (tid < 16) {
            float s = 0.f;
            #pragma unroll
            for (int w2 = 0; w2 < 12; ++w2) s += sh_p[w2][tid];
            int group = tid >> 1;
            int cta96 = blockIdx.y * 2 + blockIdx.x;
            g_part[((b * NGRP + group) * 96 + cta96) * 2 + (tid & 1)] = s;
        }
    }
}

// ---------------- stage 5a: GN finalize ----------------
__global__ void gnfin_kernel() {
    int bg = blockIdx.x;
    int t = threadIdx.x;
    __shared__ float s1[128], s2[128];
    float a = 0.f, c = 0.f;
    if (t < 96) {
        a = g_part[(bg * 96 + t) * 2];
        c = g_part[(bg * 96 + t) * 2 + 1];
    }
    s1[t] = a; s2[t] = c;
    __syncthreads();
    for (int st = 64; st > 0; st >>= 1) {
        if (t < st) { s1[t] += s1[t + st]; s2[t] += s2[t + st]; }
        __syncthreads();
    }
    if (t == 0) {
        const double N = 8.0 * HW;
        double mean = (double)s1[0] / N;
        double var  = (double)s2[0] / N - mean * mean;
        g_mean[bg] = (float)mean;
        g_rstd[bg] = (float)rsqrt(var + 1e-5);
    }
}

// ---------------- stage 5b: normalize + affine + LeakyReLU ----------------
__global__ void norm_kernel(float* __restrict__ y,
                            const float* __restrict__ gamma,
                            const float* __restrict__ beta) {
    int bc = blockIdx.y;
    int c  = bc & 63;
    int bg = bc >> 3;
    float mu = g_mean[bg], rs = g_rstd[bg];
    float ga = gamma[c] * rs;
    float be = beta[c] - mu * ga;
    float4* p = (float4*)(y + (size_t)bc * HW) + blockIdx.x * 256 + threadIdx.x;
    float4 v = *p;
    v.x = fmaf(v.x, ga, be); v.x = v.x >= 0.f ? v.x : NEG_SLOPE * v.x;
    v.y = fmaf(v.y, ga, be); v.y = v.y >= 0.f ? v.y : NEG_SLOPE * v.y;
    v.z = fmaf(v.z, ga, be); v.z = v.z >= 0.f ? v.z : NEG_SLOPE * v.z;
    v.w = fmaf(v.w, ga, be); v.w = v.w >= 0.f ? v.w : NEG_SLOPE * v.w;
    *p = v;
}

// ---------------- launch ----------------
extern "C" void kernel_launch(void* const* d_in, const int* in_sizes, int n_in,
                              void* d_out, int out_size) {
    const float* x     = (const float*)d_in[0];
    const float* w1    = (const float*)d_in[1];
    const float* w2    = (const float*)d_in[2];
    const float* b2    = (const float*)d_in[3];
    const float* w     = (const float*)d_in[4];
    const float* gamma = (const float*)d_in[5];
    const float* beta  = (const float*)d_in[6];
    float* y = (float*)d_out;

    cudaFuncSetAttribute(conv_mma_kernel,
                         cudaFuncAttributeMaxDynamicSharedMemorySize, CONV_SMEM);

    prep_kernel<<<dim3(HH, NB), 256>>>(x);
    pool2_kernel<<<4, 256>>>();
    attn_kernel<<<1, 32>>>(w1, w2, b2);
    filter_frag_kernel<<<(NB * 9 * 512 + 255) / 256, 256>>>(w);

    dim3 g(WW / TCOLS, HH / TROWS, NB);
    conv_mma_kernel<<<g, NTHR, CONV_SMEM>>>(y);

    gnfin_kernel<<<NB * NGRP, 128>>>();
    dim3 gn(HW / 1024, NB * COUT);
    norm_kernel<<<gn, 256>>>(y, gamma, beta);
}